// round 4
// baseline (speedup 1.0000x reference)
#include <cuda_runtime.h>
#include <math.h>

#define BB 8192
#define DD 256
#define NCLS 128
#define INVT 20.0f
#define NCHUNK 4
#define CHUNKC (BB/NCHUNK)   // 2048
#define TM 128
#define TN 128
#define BKK 16
#define HCAP (1<<20)

// ---- scratch (no allocations allowed) ----
__device__ int   g_lab[BB];           // decoded int labels
__device__ float g_fn[BB*DD];         // normalized features
__device__ float g_S[NCLS*DD];        // per-class sums of normalized features
__device__ int   g_cnt[NCLS];         // per-class counts
__device__ float g_pm[NCHUNK*BB];     // per-(chunk,row) running max
__device__ float g_ps[NCHUNK*BB];     // per-(chunk,row) running sum exp(sim - max)
__device__ float g_possum[BB];        // f_i . S_{label_i}
__device__ float g_selfdot[BB];       // f_i . f_i
__device__ float g_rowmax[BB];
__device__ float g_hsum[BB];
__device__ int   g_hcnt[BB];
__device__ int   g_hn;
__device__ int   g_hrow[HCAP];
__device__ float g_hval[HCAP];

// Decode labels (runtime int32-vs-int64 detection) + zero scratch.
// int64 little-endian values in [0,100) have all-zero high words; genuine
// int32 labels have random values at odd indices -> detection is safe.
__global__ void prep_kernel(const int* __restrict__ labraw) {
    __shared__ int is64_s;
    if (threadIdx.x == 0) {
        int all0 = 1;
        #pragma unroll
        for (int i = 0; i < 64; i++) all0 &= (labraw[2*i + 1] == 0);
        is64_s = all0;
    }
    __syncthreads();
    int is64 = is64_s;
    int tid = blockIdx.x*blockDim.x + threadIdx.x;
    int nt = gridDim.x*blockDim.x;
    for (int i = tid; i < BB; i += nt)
        g_lab[i] = is64 ? labraw[2*i] : labraw[i];
    for (int i = tid; i < NCLS*DD; i += nt) g_S[i] = 0.f;
    for (int i = tid; i < NCLS; i += nt) g_cnt[i] = 0;
    for (int i = tid; i < BB; i += nt) { g_hsum[i] = 0.f; g_hcnt[i] = 0; }
    if (tid == 0) g_hn = 0;
}

// one warp per row: L2-normalize, write g_fn, accumulate class sums/counts
__global__ void norm_kernel(const float* __restrict__ feat) {
    int warp = threadIdx.x >> 5, lane = threadIdx.x & 31;
    int row = blockIdx.x*8 + warp;
    const float* fr = feat + (size_t)row*DD;
    float v[8]; float ss = 0.f;
    #pragma unroll
    for (int j = 0; j < 8; j++) { v[j] = fr[lane + j*32]; ss += v[j]*v[j]; }
    #pragma unroll
    for (int off = 16; off > 0; off >>= 1) ss += __shfl_xor_sync(0xffffffffu, ss, off);
    float inv = 1.f / fmaxf(sqrtf(ss), 1e-12f);
    int c = g_lab[row];
    float* fo = g_fn + (size_t)row*DD;
    #pragma unroll
    for (int j = 0; j < 8; j++) {
        float fnv = v[j]*inv;
        fo[lane + j*32] = fnv;
        atomicAdd(&g_S[c*DD + lane + j*32], fnv);
    }
    if (lane == 0) atomicAdd(&g_cnt[c], 1);
}

// one warp per row: dot(f_i, S_c) and dot(f_i, f_i)
__global__ void possum_kernel() {
    int warp = threadIdx.x >> 5, lane = threadIdx.x & 31;
    int row = blockIdx.x*8 + warp;
    int c = g_lab[row];
    const float* fr = g_fn + (size_t)row*DD;
    const float* sc = g_S + c*DD;
    float dp = 0.f, sd = 0.f;
    #pragma unroll
    for (int j = 0; j < 8; j++) {
        float a = fr[lane + j*32];
        dp += a*sc[lane + j*32];
        sd += a*a;
    }
    #pragma unroll
    for (int off = 16; off > 0; off >>= 1) {
        dp += __shfl_xor_sync(0xffffffffu, dp, off);
        sd += __shfl_xor_sync(0xffffffffu, sd, off);
    }
    if (lane == 0) { g_possum[row] = dp; g_selfdot[row] = sd; }
}

// Fused GEMM + online row softmax stats. Each CTA: 128 rows x 2048-col chunk.
__global__ void __launch_bounds__(256, 2)
main_kernel() {
    __shared__ float As[BKK][TM];
    __shared__ float Bs[BKK][TN];
    int tid = threadIdx.x;
    int tx = tid & 15, ty = tid >> 4;
    int rowbase = blockIdx.x * TM;
    int chunk = blockIdx.y;
    int colstart = chunk * CHUNKC;

    float M[8], S[8];
    #pragma unroll
    for (int r = 0; r < 8; r++) { M[r] = -INFINITY; S[r] = 0.f; }

    for (int ct = 0; ct < CHUNKC/TN; ++ct) {
        int colbase = colstart + ct*TN;
        float acc[8][8];
        #pragma unroll
        for (int r = 0; r < 8; r++)
            #pragma unroll
            for (int c = 0; c < 8; c++) acc[r][c] = 0.f;

        for (int kb = 0; kb < DD; kb += BKK) {
            #pragma unroll
            for (int it = 0; it < 2; ++it) {
                int v = tid + it*256;
                int row = v >> 2;
                int kq = (v & 3) << 2;
                float4 a = *reinterpret_cast<const float4*>(
                    &g_fn[(size_t)(rowbase+row)*DD + kb + kq]);
                As[kq+0][row] = a.x; As[kq+1][row] = a.y;
                As[kq+2][row] = a.z; As[kq+3][row] = a.w;
                float4 b = *reinterpret_cast<const float4*>(
                    &g_fn[(size_t)(colbase+row)*DD + kb + kq]);
                Bs[kq+0][row] = b.x; Bs[kq+1][row] = b.y;
                Bs[kq+2][row] = b.z; Bs[kq+3][row] = b.w;
            }
            __syncthreads();
            #pragma unroll
            for (int k = 0; k < BKK; k++) {
                float4 a0 = *reinterpret_cast<const float4*>(&As[k][ty*8]);
                float4 a1 = *reinterpret_cast<const float4*>(&As[k][ty*8+4]);
                float4 b0 = *reinterpret_cast<const float4*>(&Bs[k][tx*8]);
                float4 b1 = *reinterpret_cast<const float4*>(&Bs[k][tx*8+4]);
                float ar[8] = {a0.x,a0.y,a0.z,a0.w,a1.x,a1.y,a1.z,a1.w};
                float br[8] = {b0.x,b0.y,b0.z,b0.w,b1.x,b1.y,b1.z,b1.w};
                #pragma unroll
                for (int r = 0; r < 8; r++)
                    #pragma unroll
                    for (int c = 0; c < 8; c++)
                        acc[r][c] = fmaf(ar[r], br[c], acc[r][c]);
            }
            __syncthreads();
        }

        // epilogue: per-row online (max, sumexp); diag in max, excluded from sum
        #pragma unroll
        for (int r = 0; r < 8; r++) {
            int gr = rowbase + ty*8 + r;
            float vv[8]; float mloc = -INFINITY;
            #pragma unroll
            for (int c = 0; c < 8; c++) {
                vv[c] = acc[r][c]*INVT;
                mloc = fmaxf(mloc, vv[c]);
            }
            float sloc = 0.f;
            #pragma unroll
            for (int c = 0; c < 8; c++) {
                int gc = colbase + tx*8 + c;
                float e = __expf(vv[c] - mloc);
                sloc += (gc == gr) ? 0.f : e;
                if (acc[r][c] > 0.7f && gc != gr) {        // rare path
                    if (g_lab[gr] == g_lab[gc]) {
                        int idx = atomicAdd(&g_hn, 1);
                        if (idx < HCAP) { g_hrow[idx] = gr; g_hval[idx] = vv[c]; }
                    }
                }
            }
            // butterfly-merge across the 16 lanes sharing this row
            #pragma unroll
            for (int off = 1; off < 16; off <<= 1) {
                float om = __shfl_xor_sync(0xffffffffu, mloc, off);
                float os = __shfl_xor_sync(0xffffffffu, sloc, off);
                float nm = fmaxf(mloc, om);
                sloc = sloc*__expf(mloc - nm) + os*__expf(om - nm);
                mloc = nm;
            }
            float nm = fmaxf(M[r], mloc);
            S[r] = S[r]*__expf(M[r] - nm) + sloc*__expf(mloc - nm);
            M[r] = nm;
        }
    }
    if (tx == 0) {
        #pragma unroll
        for (int r = 0; r < 8; r++) {
            int gr = rowbase + ty*8 + r;
            g_pm[chunk*BB + gr] = M[r];
            g_ps[chunk*BB + gr] = S[r];
        }
    }
}

__global__ void finalize_kernel(float* __restrict__ out) {
    int tid = threadIdx.x;
    double accscl = 0.0, accrel = 0.0;
    for (int i = tid; i < BB; i += 1024) {
        float m = g_pm[i]; float s = g_ps[i];
        #pragma unroll
        for (int k = 1; k < NCHUNK; k++) {
            float mk = g_pm[k*BB + i], sk = g_ps[k*BB + i];
            float nm = fmaxf(m, mk);
            s = s*__expf(m - nm) + sk*__expf(mk - nm);
            m = nm;
        }
        float logd = logf(s + 1e-12f) + m;
        int c = g_lab[i];
        float np = (float)(g_cnt[c] - 1);
        float pos = (g_possum[i] - g_selfdot[i]) * INVT;
        accscl += (double)np*(double)logd - (double)pos;
        g_rowmax[i] = m;
    }
    __syncthreads();
    int hn = g_hn; if (hn > HCAP) hn = HCAP;
    if (hn > 0) {
        for (int e = tid; e < hn; e += 1024) {
            int r = g_hrow[e];
            atomicAdd(&g_hsum[r], __expf(g_hval[e] - g_rowmax[r]));
            atomicAdd(&g_hcnt[r], 1);
        }
        __syncthreads();
        for (int i = tid; i < BB; i += 1024) {
            if (g_hcnt[i] > 0)
                accrel += (double)logf(g_hsum[i] + __expf(INVT - g_rowmax[i]));
        }
    }
    __shared__ double s1[1024], s2[1024];
    s1[tid] = accscl; s2[tid] = accrel;
    __syncthreads();
    for (int st = 512; st > 0; st >>= 1) {
        if (tid < st) { s1[tid] += s1[tid+st]; s2[tid] += s2[tid+st]; }
        __syncthreads();
    }
    if (tid == 0) {
        double npos = 0.0;
        for (int c = 0; c < NCLS; c++) {
            double cc = (double)g_cnt[c];
            npos += cc*(cc - 1.0);
        }
        double scl = (npos > 0.0) ? s1[0] / fmax(npos, 1.0) : 0.0;
        int hn2 = g_hn; if (hn2 > HCAP) hn2 = HCAP;
        double rel = (hn2 > 0) ? s2[0] / (double)(hn2 > 1 ? hn2 : 1) : 0.0;
        double tot = scl + rel;
        tot = fmin(fmax(tot, 0.0), 10.0);
        out[0] = (float)tot;
    }
}

extern "C" void kernel_launch(void* const* d_in, const int* in_sizes, int n_in,
                              void* d_out, int out_size) {
    const float* feat = (const float*)d_in[0];
    const int* labraw = (const int*)d_in[1];
    float* out = (float*)d_out;

    prep_kernel<<<64, 256>>>(labraw);
    norm_kernel<<<BB/8, 256>>>(feat);
    possum_kernel<<<BB/8, 256>>>();
    main_kernel<<<dim3(BB/TM, NCHUNK), 256>>>();
    finalize_kernel<<<1, 1024>>>(out);
}

// round 7
// speedup vs baseline: 2.6872x; 2.6872x over previous
#include <cuda_runtime.h>
#include <cuda_bf16.h>
#include <math.h>
#include <cstdint>

#define BB 8192
#define DD 256
#define NCLS 128
#define HCAP (1<<20)

// ---------------- scratch ----------------
__device__ int   g_lab[BB];
__device__ float g_fn[BB*DD];
__device__ __nv_bfloat16 g_hi[BB*DD];
__device__ __nv_bfloat16 g_lo[BB*DD];
__device__ float g_S[NCLS*DD];
__device__ int   g_cnt[NCLS];
__device__ float g_rowsum[BB];
__device__ float g_possum[BB];
__device__ float g_selfdot[BB];
__device__ float g_hsum[BB];
__device__ int   g_hcnt[BB];
__device__ int   g_hn;
__device__ int   g_hrow[HCAP];
__device__ float g_hval[HCAP];

__device__ __forceinline__ uint32_t smem_u32(const void* p) {
    uint32_t a;
    asm("{ .reg .u64 t; cvta.to.shared.u64 t, %1; cvt.u32.u64 %0, t; }" : "=r"(a) : "l"(p));
    return a;
}

#define LDM_X4(r0,r1,r2,r3,addr) \
    asm volatile("ldmatrix.sync.aligned.m8n8.x4.shared.b16 {%0,%1,%2,%3}, [%4];" \
        : "=r"(r0), "=r"(r1), "=r"(r2), "=r"(r3) : "r"(addr))

#define MMA_BF16(c, a0,a1,a2,a3, b0,b1) \
    asm volatile("mma.sync.aligned.m16n8k16.row.col.f32.bf16.bf16.f32 " \
        "{%0,%1,%2,%3}, {%4,%5,%6,%7}, {%8,%9}, {%0,%1,%2,%3};" \
        : "+f"((c)[0]), "+f"((c)[1]), "+f"((c)[2]), "+f"((c)[3]) \
        : "r"(a0), "r"(a1), "r"(a2), "r"(a3), "r"(b0), "r"(b1))

// fast e^{20x}: 2^{x*20*log2e}, degree-6 poly, relerr ~1e-7
__device__ __forceinline__ float exp20(float x) {
    float y = x * 28.853900817779268f;
    float z = y + 12582912.0f;
    int   zi = __float_as_int(z);
    float f = y - (z - 12582912.0f);
    float p = 1.5403530e-4f;
    p = fmaf(p, f, 1.3333558e-3f);
    p = fmaf(p, f, 9.6181291e-3f);
    p = fmaf(p, f, 5.5504109e-2f);
    p = fmaf(p, f, 2.4022651e-1f);
    p = fmaf(p, f, 6.9314718e-1f);
    p = fmaf(p, f, 1.0f);
    return __int_as_float(__float_as_int(p) + (zi << 23));
}

// ---------------- prep ----------------
__global__ void prep_kernel(const int* __restrict__ labraw) {
    __shared__ int is64_s;
    if (threadIdx.x == 0) {
        int all0 = 1;
        #pragma unroll
        for (int i = 0; i < 64; i++) all0 &= (labraw[2*i + 1] == 0);
        is64_s = all0;
    }
    __syncthreads();
    int is64 = is64_s;
    int tid = blockIdx.x*blockDim.x + threadIdx.x;
    int nt = gridDim.x*blockDim.x;
    for (int i = tid; i < BB; i += nt) g_lab[i] = is64 ? labraw[2*i] : labraw[i];
    for (int i = tid; i < NCLS*DD; i += nt) g_S[i] = 0.f;
    for (int i = tid; i < NCLS; i += nt) g_cnt[i] = 0;
    for (int i = tid; i < BB; i += nt) { g_hsum[i] = 0.f; g_hcnt[i] = 0; g_rowsum[i] = 0.f; }
    if (tid == 0) g_hn = 0;
}

// ---------------- normalize + bf16 split ----------------
__global__ void norm_kernel(const float* __restrict__ feat) {
    int warp = threadIdx.x >> 5, lane = threadIdx.x & 31;
    int row = blockIdx.x*8 + warp;
    const float* fr = feat + (size_t)row*DD;
    float v[8]; float ss = 0.f;
    #pragma unroll
    for (int j = 0; j < 8; j++) { v[j] = fr[lane + j*32]; ss += v[j]*v[j]; }
    #pragma unroll
    for (int off = 16; off > 0; off >>= 1) ss += __shfl_xor_sync(0xffffffffu, ss, off);
    float inv = 1.f / fmaxf(sqrtf(ss), 1e-12f);
    int c = g_lab[row];
    float* fo = g_fn + (size_t)row*DD;
    #pragma unroll
    for (int j = 0; j < 8; j++) {
        float fnv = v[j]*inv;
        fo[lane + j*32] = fnv;
        __nv_bfloat16 h = __float2bfloat16(fnv);
        g_hi[(size_t)row*DD + lane + j*32] = h;
        g_lo[(size_t)row*DD + lane + j*32] = __float2bfloat16(fnv - __bfloat162float(h));
        atomicAdd(&g_S[c*DD + lane + j*32], fnv);
    }
    if (lane == 0) atomicAdd(&g_cnt[c], 1);
}

__global__ void possum_kernel() {
    int warp = threadIdx.x >> 5, lane = threadIdx.x & 31;
    int row = blockIdx.x*8 + warp;
    int c = g_lab[row];
    const float* fr = g_fn + (size_t)row*DD;
    const float* sc = g_S + c*DD;
    float dp = 0.f, sd = 0.f;
    #pragma unroll
    for (int j = 0; j < 8; j++) {
        float a = fr[lane + j*32];
        dp += a*sc[lane + j*32];
        sd += a*a;
    }
    #pragma unroll
    for (int off = 16; off > 0; off >>= 1) {
        dp += __shfl_xor_sync(0xffffffffu, dp, off);
        sd += __shfl_xor_sync(0xffffffffu, sd, off);
    }
    if (lane == 0) { g_possum[row] = dp; g_selfdot[row] = sd; }
}

// ---------------- mma.sync main kernel ----------------
// SMEM: A tiles (128 x 256, stride 264) hi+lo, B chunk (128 x 128, stride 136) hi+lo
#define ASTR 264
#define BSTR 136
#define SM_AHI 0
#define SM_ALO (SM_AHI + 128*ASTR*2)           // 67584
#define SM_BHI (SM_ALO + 128*ASTR*2)           // 135168
#define SM_BLO (SM_BHI + 128*BSTR*2)           // 169984
#define SM_TOTAL (SM_BLO + 128*BSTR*2)         // 204800

__global__ void __launch_bounds__(256)
main_tc() {
    extern __shared__ char smem[];
    uint32_t sb = smem_u32(smem);
    int tid = threadIdx.x;
    int wid = tid >> 5, l = tid & 31;
    int warpM = wid >> 2;          // 0..1 -> 64-row half
    int warpN = wid & 3;           // 0..3 -> 32-col quarter
    int rowbase = blockIdx.x * 128;

    // ---- load A tiles (hi + lo), 128 rows x 256 k ----
    for (int idx = tid; idx < 4096; idx += 256) {
        int row = idx >> 5, k = (idx & 31)*8;
        uint32_t off = (uint32_t)(row*ASTR + k)*2;
        *reinterpret_cast<uint4*>(smem + SM_AHI + off) =
            *reinterpret_cast<const uint4*>(&g_hi[(size_t)(rowbase+row)*DD + k]);
        *reinterpret_cast<uint4*>(smem + SM_ALO + off) =
            *reinterpret_cast<const uint4*>(&g_lo[(size_t)(rowbase+row)*DD + k]);
    }
    __syncthreads();

    // per-lane ldmatrix offsets
    uint32_t aOff = (uint32_t)((warpM*64 + (l & 15))*ASTR*2 + (l >> 4)*16);
    int bRow = (l & 7) + ((l >> 4) << 3);
    uint32_t bOff = (uint32_t)((warpN*32 + bRow)*BSTR*2 + ((l >> 3) & 1)*16);

    float rs[8];
    #pragma unroll
    for (int i = 0; i < 8; i++) rs[i] = 0.f;

    for (int ct = 0; ct < 16; ++ct) {
        int colbase = blockIdx.y*2048 + ct*128;
        float acc[64];
        #pragma unroll
        for (int i = 0; i < 64; i++) acc[i] = 0.f;

        #pragma unroll
        for (int kc = 0; kc < 2; ++kc) {
            // load B chunk: 128 cols x 128 k (hi + lo)
            for (int idx = tid; idx < 2048; idx += 256) {
                int row = idx >> 4, k = (idx & 15)*8;
                uint32_t off = (uint32_t)(row*BSTR + k)*2;
                size_t src = (size_t)(colbase+row)*DD + kc*128 + k;
                *reinterpret_cast<uint4*>(smem + SM_BHI + off) =
                    *reinterpret_cast<const uint4*>(&g_hi[src]);
                *reinterpret_cast<uint4*>(smem + SM_BLO + off) =
                    *reinterpret_cast<const uint4*>(&g_lo[src]);
            }
            __syncthreads();

            #pragma unroll
            for (int ks = 0; ks < 8; ++ks) {
                int gk = kc*8 + ks;
                uint32_t ah[16], al[16], bh[8], bl[8];
                #pragma unroll
                for (int mt = 0; mt < 4; ++mt) {
                    uint32_t a = sb + aOff + (uint32_t)(mt*16*ASTR*2 + gk*32);
                    LDM_X4(ah[mt*4+0], ah[mt*4+1], ah[mt*4+2], ah[mt*4+3], a + SM_AHI);
                    LDM_X4(al[mt*4+0], al[mt*4+1], al[mt*4+2], al[mt*4+3], a + SM_ALO);
                }
                {
                    uint32_t b0 = sb + bOff + (uint32_t)(ks*32);
                    uint32_t b1 = b0 + 16*BSTR*2;
                    LDM_X4(bh[0], bh[1], bh[2], bh[3], b0 + SM_BHI);
                    LDM_X4(bh[4], bh[5], bh[6], bh[7], b1 + SM_BHI);
                    LDM_X4(bl[0], bl[1], bl[2], bl[3], b0 + SM_BLO);
                    LDM_X4(bl[4], bl[5], bl[6], bl[7], b1 + SM_BLO);
                }
                #pragma unroll
                for (int mt = 0; mt < 4; ++mt)
                    #pragma unroll
                    for (int nt = 0; nt < 4; ++nt) {
                        float* c = &acc[(mt*4+nt)*4];
                        MMA_BF16(c, ah[mt*4+0], ah[mt*4+1], ah[mt*4+2], ah[mt*4+3],
                                 bh[nt*2+0], bh[nt*2+1]);
                        MMA_BF16(c, ah[mt*4+0], ah[mt*4+1], ah[mt*4+2], ah[mt*4+3],
                                 bl[nt*2+0], bl[nt*2+1]);
                        MMA_BF16(c, al[mt*4+0], al[mt*4+1], al[mt*4+2], al[mt*4+3],
                                 bh[nt*2+0], bh[nt*2+1]);
                    }
            }
            __syncthreads();
        }

        // ---- epilogue for this 128x128 tile ----
        int grq = rowbase + warpM*64 + (l >> 2);
        #pragma unroll
        for (int mt = 0; mt < 4; ++mt) {
            int gr0 = grq + mt*16;
            int gr1 = gr0 + 8;
            float s0 = 0.f, s1 = 0.f;
            #pragma unroll
            for (int nt = 0; nt < 4; ++nt) {
                const float* c = &acc[(mt*4+nt)*4];
                int gc0 = colbase + warpN*32 + nt*8 + (l & 3)*2;
                int gc1 = gc0 + 1;
                float e0 = exp20(c[0]);
                float e1 = exp20(c[1]);
                float e2 = exp20(c[2]);
                float e3 = exp20(c[3]);
                s0 += (gc0 == gr0) ? 0.f : e0;
                s0 += (gc1 == gr0) ? 0.f : e1;
                s1 += (gc0 == gr1) ? 0.f : e2;
                s1 += (gc1 == gr1) ? 0.f : e3;
                // rare path: cosine > 0.7 and same label
                if (c[0] > 0.7f && gc0 != gr0) {
                    if (g_lab[gc0] == g_lab[gr0]) {
                        int idx = atomicAdd(&g_hn, 1);
                        if (idx < HCAP) { g_hrow[idx] = gr0; g_hval[idx] = c[0]*20.f; }
                    }
                }
                if (c[1] > 0.7f && gc1 != gr0) {
                    if (g_lab[gc1] == g_lab[gr0]) {
                        int idx = atomicAdd(&g_hn, 1);
                        if (idx < HCAP) { g_hrow[idx] = gr0; g_hval[idx] = c[1]*20.f; }
                    }
                }
                if (c[2] > 0.7f && gc0 != gr1) {
                    if (g_lab[gc0] == g_lab[gr1]) {
                        int idx = atomicAdd(&g_hn, 1);
                        if (idx < HCAP) { g_hrow[idx] = gr1; g_hval[idx] = c[2]*20.f; }
                    }
                }
                if (c[3] > 0.7f && gc1 != gr1) {
                    if (g_lab[gc1] == g_lab[gr1]) {
                        int idx = atomicAdd(&g_hn, 1);
                        if (idx < HCAP) { g_hrow[idx] = gr1; g_hval[idx] = c[3]*20.f; }
                    }
                }
            }
            rs[mt*2+0] += s0;
            rs[mt*2+1] += s1;
        }
    }

    // quad-reduce (lanes with same l>>2 share rows) and emit
    #pragma unroll
    for (int i = 0; i < 8; i++) {
        rs[i] += __shfl_xor_sync(0xffffffffu, rs[i], 1);
        rs[i] += __shfl_xor_sync(0xffffffffu, rs[i], 2);
    }
    if ((l & 3) == 0) {
        #pragma unroll
        for (int i = 0; i < 8; i++) {
            int row = rowbase + warpM*64 + (i >> 1)*16 + (i & 1)*8 + (l >> 2);
            atomicAdd(&g_rowsum[row], rs[i]);
        }
    }
}

// ---------------- finalize ----------------
__global__ void finalize_kernel(float* __restrict__ out) {
    int tid = threadIdx.x;
    double accscl = 0.0, accrel = 0.0;
    for (int i = tid; i < BB; i += 1024) {
        float logd = logf(g_rowsum[i] + 1e-30f);
        int c = g_lab[i];
        float np = (float)(g_cnt[c] - 1);
        float pos = (g_possum[i] - g_selfdot[i]) * 20.f;
        accscl += (double)np*(double)logd - (double)pos;
    }
    __syncthreads();
    int hn = g_hn; if (hn > HCAP) hn = HCAP;
    if (hn > 0) {
        for (int e = tid; e < hn; e += 1024) {
            int r = g_hrow[e];
            atomicAdd(&g_hsum[r], __expf(g_hval[e] - 20.f));
            atomicAdd(&g_hcnt[r], 1);
        }
        __syncthreads();
        for (int i = tid; i < BB; i += 1024) {
            if (g_hcnt[i] > 0)
                accrel += (double)log1pf(g_hsum[i]);
        }
    }
    __shared__ double s1[1024], s2[1024];
    s1[tid] = accscl; s2[tid] = accrel;
    __syncthreads();
    for (int st = 512; st > 0; st >>= 1) {
        if (tid < st) { s1[tid] += s1[tid+st]; s2[tid] += s2[tid+st]; }
        __syncthreads();
    }
    if (tid == 0) {
        double npos = 0.0;
        for (int c = 0; c < NCLS; c++) {
            double cc = (double)g_cnt[c];
            npos += cc*(cc - 1.0);
        }
        double scl = (npos > 0.0) ? s1[0] / fmax(npos, 1.0) : 0.0;
        int hn2 = g_hn; if (hn2 > HCAP) hn2 = HCAP;
        double rel = (hn2 > 0) ? s2[0] / (double)(hn2 > 1 ? hn2 : 1) : 0.0;
        double tot = scl + rel;
        tot = fmin(fmax(tot, 0.0), 10.0);
        out[0] = (float)tot;
    }
}

extern "C" void kernel_launch(void* const* d_in, const int* in_sizes, int n_in,
                              void* d_out, int out_size) {
    const float* feat = (const float*)d_in[0];
    const int* labraw = (const int*)d_in[1];
    float* out = (float*)d_out;

    static bool attr_set = false;
    if (!attr_set) {
        cudaFuncSetAttribute(main_tc, cudaFuncAttributeMaxDynamicSharedMemorySize, SM_TOTAL);
        attr_set = true;
    }

    prep_kernel<<<64, 256>>>(labraw);
    norm_kernel<<<BB/8, 256>>>(feat);
    possum_kernel<<<BB/8, 256>>>();
    main_tc<<<dim3(64, 4), 256, SM_TOTAL>>>();
    finalize_kernel<<<1, 1024>>>(out);
}

// round 8
// speedup vs baseline: 4.4913x; 1.6714x over previous
#include <cuda_runtime.h>
#include <cuda_bf16.h>
#include <math.h>
#include <cstdint>

#define BB 8192
#define DD 256
#define NCLS 128
#define HCAP (1<<20)

// ---------------- scratch ----------------
__device__ int   g_lab[BB];
__device__ float g_fn[BB*DD];
__device__ __nv_bfloat16 g_hi[BB*DD];
__device__ __nv_bfloat16 g_lo[BB*DD];
__device__ float g_S[NCLS*DD];
__device__ int   g_cnt[NCLS];
__device__ float g_rowsum[BB];
__device__ float g_possum[BB];
__device__ float g_selfdot[BB];
__device__ float g_hsum[BB];
__device__ int   g_hcnt[BB];
__device__ int   g_hn;
__device__ int   g_hrow[HCAP];
__device__ float g_hval[HCAP];

__device__ __forceinline__ uint32_t smem_u32(const void* p) {
    uint32_t a;
    asm("{ .reg .u64 t; cvta.to.shared.u64 t, %1; cvt.u32.u64 %0, t; }" : "=r"(a) : "l"(p));
    return a;
}

#define LDM_X4(r0,r1,r2,r3,addr) \
    asm volatile("ldmatrix.sync.aligned.m8n8.x4.shared.b16 {%0,%1,%2,%3}, [%4];" \
        : "=r"(r0), "=r"(r1), "=r"(r2), "=r"(r3) : "r"(addr))

#define MMA_BF16(c, a0,a1,a2,a3, b0,b1) \
    asm volatile("mma.sync.aligned.m16n8k16.row.col.f32.bf16.bf16.f32 " \
        "{%0,%1,%2,%3}, {%4,%5,%6,%7}, {%8,%9}, {%0,%1,%2,%3};" \
        : "+f"((c)[0]), "+f"((c)[1]), "+f"((c)[2]), "+f"((c)[3]) \
        : "r"(a0), "r"(a1), "r"(a2), "r"(a3), "r"(b0), "r"(b1))

__device__ __forceinline__ void cp16(uint32_t dst, const void* src) {
    asm volatile("cp.async.cg.shared.global [%0], [%1], 16;" :: "r"(dst), "l"(src));
}
#define CP_COMMIT() asm volatile("cp.async.commit_group;" ::: "memory")
#define CP_WAIT(n)  asm volatile("cp.async.wait_group %0;" :: "n"(n) : "memory")

// fast e^{20x}: 2^{x*20*log2e}, degree-6 poly, relerr ~1e-7
__device__ __forceinline__ float exp20(float x) {
    float y = x * 28.853900817779268f;
    float z = y + 12582912.0f;
    int   zi = __float_as_int(z);
    float f = y - (z - 12582912.0f);
    float p = 1.5403530e-4f;
    p = fmaf(p, f, 1.3333558e-3f);
    p = fmaf(p, f, 9.6181291e-3f);
    p = fmaf(p, f, 5.5504109e-2f);
    p = fmaf(p, f, 2.4022651e-1f);
    p = fmaf(p, f, 6.9314718e-1f);
    p = fmaf(p, f, 1.0f);
    return __int_as_float(__float_as_int(p) + (zi << 23));
}

// ---------------- prep ----------------
__global__ void prep_kernel(const int* __restrict__ labraw) {
    __shared__ int is64_s;
    if (threadIdx.x == 0) {
        int all0 = 1;
        #pragma unroll
        for (int i = 0; i < 64; i++) all0 &= (labraw[2*i + 1] == 0);
        is64_s = all0;
    }
    __syncthreads();
    int is64 = is64_s;
    int tid = blockIdx.x*blockDim.x + threadIdx.x;
    int nt = gridDim.x*blockDim.x;
    for (int i = tid; i < BB; i += nt) g_lab[i] = is64 ? labraw[2*i] : labraw[i];
    for (int i = tid; i < NCLS*DD; i += nt) g_S[i] = 0.f;
    for (int i = tid; i < NCLS; i += nt) g_cnt[i] = 0;
    for (int i = tid; i < BB; i += nt) { g_hsum[i] = 0.f; g_hcnt[i] = 0; g_rowsum[i] = 0.f; }
    if (tid == 0) g_hn = 0;
}

// ---------------- normalize + bf16 split ----------------
__global__ void norm_kernel(const float* __restrict__ feat) {
    int warp = threadIdx.x >> 5, lane = threadIdx.x & 31;
    int row = blockIdx.x*8 + warp;
    const float* fr = feat + (size_t)row*DD;
    float v[8]; float ss = 0.f;
    #pragma unroll
    for (int j = 0; j < 8; j++) { v[j] = fr[lane + j*32]; ss += v[j]*v[j]; }
    #pragma unroll
    for (int off = 16; off > 0; off >>= 1) ss += __shfl_xor_sync(0xffffffffu, ss, off);
    float inv = 1.f / fmaxf(sqrtf(ss), 1e-12f);
    int c = g_lab[row];
    float* fo = g_fn + (size_t)row*DD;
    #pragma unroll
    for (int j = 0; j < 8; j++) {
        float fnv = v[j]*inv;
        fo[lane + j*32] = fnv;
        __nv_bfloat16 h = __float2bfloat16(fnv);
        g_hi[(size_t)row*DD + lane + j*32] = h;
        g_lo[(size_t)row*DD + lane + j*32] = __float2bfloat16(fnv - __bfloat162float(h));
        atomicAdd(&g_S[c*DD + lane + j*32], fnv);
    }
    if (lane == 0) atomicAdd(&g_cnt[c], 1);
}

__global__ void possum_kernel() {
    int warp = threadIdx.x >> 5, lane = threadIdx.x & 31;
    int row = blockIdx.x*8 + warp;
    int c = g_lab[row];
    const float* fr = g_fn + (size_t)row*DD;
    const float* sc = g_S + c*DD;
    float dp = 0.f, sd = 0.f;
    #pragma unroll
    for (int j = 0; j < 8; j++) {
        float a = fr[lane + j*32];
        dp += a*sc[lane + j*32];
        sd += a*a;
    }
    #pragma unroll
    for (int off = 16; off > 0; off >>= 1) {
        dp += __shfl_xor_sync(0xffffffffu, dp, off);
        sd += __shfl_xor_sync(0xffffffffu, sd, off);
    }
    if (lane == 0) { g_possum[row] = dp; g_selfdot[row] = sd; }
}

// ---------------- triangular mma.sync main kernel ----------------
// One 128x128 output tile per CTA, tiles only for rb <= cb (symmetry).
// K chunked by 64, cp.async double-buffered.
#define KC 64
#define STR 72                       // 64 k elems + 8 pad
#define MAT (128*STR*2)              // 18432 B per matrix-half per stage
#define STAGE (4*MAT)                // Ahi, Alo, Bhi, Blo
#define SM_TOTAL (2*STAGE)           // 147456 B

__device__ __forceinline__ void load_chunk(uint32_t sb, int stage,
                                           int rowbase, int colbase, int kc) {
    int tid = threadIdx.x;
    uint32_t sbase = sb + stage*STAGE;
    #pragma unroll
    for (int m = 0; m < 4; m++) {
        int base = (m < 2) ? rowbase : colbase;
        const __nv_bfloat16* src = (m & 1) ? g_lo : g_hi;
        #pragma unroll
        for (int i = 0; i < 4; i++) {
            int idx = tid + i*256;
            int row = idx >> 3;
            int kq = (idx & 7) * 8;
            uint32_t dst = sbase + m*MAT + (uint32_t)(row*STR + kq)*2;
            cp16(dst, &src[(size_t)(base+row)*DD + kc*KC + kq]);
        }
    }
}

__global__ void __launch_bounds__(256)
main_tc() {
    extern __shared__ char smem[];
    uint32_t sb = smem_u32(smem);
    int tid = threadIdx.x;
    int wid = tid >> 5, l = tid & 31;
    int warpM = wid >> 2;
    int warpN = wid & 3;

    // decode triangular tile index -> (rb, cb), rb <= cb
    int rb = 0, rem = blockIdx.x;
    while (rem >= 64 - rb) { rem -= 64 - rb; rb++; }
    int cb = rb + rem;
    int rowbase = rb * 128;
    int colbase = cb * 128;
    bool isdiag = (rb == cb);

    // per-lane ldmatrix byte offsets (within a matrix tile)
    uint32_t aOff = (uint32_t)((warpM*64 + (l & 15))*STR*2 + (l >> 4)*16);
    int bRow = (l & 7) + ((l >> 4) << 3);
    uint32_t bOff = (uint32_t)((warpN*32 + bRow)*STR*2 + ((l >> 3) & 1)*16);

    float acc[64];
    #pragma unroll
    for (int i = 0; i < 64; i++) acc[i] = 0.f;

    load_chunk(sb, 0, rowbase, colbase, 0);
    CP_COMMIT();

    #pragma unroll 1
    for (int c = 0; c < 4; ++c) {
        if (c < 3) { load_chunk(sb, (c + 1) & 1, rowbase, colbase, c + 1); CP_COMMIT(); }
        if (c < 3) CP_WAIT(1); else CP_WAIT(0);
        __syncthreads();

        uint32_t st = sb + (c & 1)*STAGE;
        uint32_t sAhi = st, sAlo = st + MAT, sBhi = st + 2*MAT, sBlo = st + 3*MAT;

        #pragma unroll
        for (int ks = 0; ks < 4; ++ks) {
            uint32_t ka = (uint32_t)(ks*32);
            uint32_t a0[16], b0h[8], b0l[8];
            #pragma unroll
            for (int mt = 0; mt < 4; ++mt) {
                uint32_t aa = sAhi + aOff + (uint32_t)(mt*16*STR*2) + ka;
                LDM_X4(a0[mt*4+0], a0[mt*4+1], a0[mt*4+2], a0[mt*4+3], aa);
            }
            {
                uint32_t bb0 = bOff + ka;
                uint32_t bb1 = bb0 + (uint32_t)(16*STR*2);
                LDM_X4(b0h[0], b0h[1], b0h[2], b0h[3], sBhi + bb0);
                LDM_X4(b0h[4], b0h[5], b0h[6], b0h[7], sBhi + bb1);
                LDM_X4(b0l[0], b0l[1], b0l[2], b0l[3], sBlo + bb0);
                LDM_X4(b0l[4], b0l[5], b0l[6], b0l[7], sBlo + bb1);
            }
            // pass 1: Ahi * Bhi   (16 independent MMAs)
            #pragma unroll
            for (int mt = 0; mt < 4; ++mt)
                #pragma unroll
                for (int nt = 0; nt < 4; ++nt)
                    MMA_BF16(&acc[(mt*4+nt)*4], a0[mt*4+0], a0[mt*4+1], a0[mt*4+2], a0[mt*4+3],
                             b0h[nt*2+0], b0h[nt*2+1]);
            // pass 2: Ahi * Blo
            #pragma unroll
            for (int mt = 0; mt < 4; ++mt)
                #pragma unroll
                for (int nt = 0; nt < 4; ++nt)
                    MMA_BF16(&acc[(mt*4+nt)*4], a0[mt*4+0], a0[mt*4+1], a0[mt*4+2], a0[mt*4+3],
                             b0l[nt*2+0], b0l[nt*2+1]);
            // reload A-lo into same regs, pass 3: Alo * Bhi
            #pragma unroll
            for (int mt = 0; mt < 4; ++mt) {
                uint32_t aa = sAlo + aOff + (uint32_t)(mt*16*STR*2) + ka;
                LDM_X4(a0[mt*4+0], a0[mt*4+1], a0[mt*4+2], a0[mt*4+3], aa);
            }
            #pragma unroll
            for (int mt = 0; mt < 4; ++mt)
                #pragma unroll
                for (int nt = 0; nt < 4; ++nt)
                    MMA_BF16(&acc[(mt*4+nt)*4], a0[mt*4+0], a0[mt*4+1], a0[mt*4+2], a0[mt*4+3],
                             b0h[nt*2+0], b0h[nt*2+1]);
        }
        __syncthreads();
    }

    // ---- epilogue: scatter exp into row sums and (off-diag) column sums ----
    float rs[8];
    float cp0[4], cp1[4];
    #pragma unroll
    for (int i = 0; i < 8; i++) rs[i] = 0.f;
    #pragma unroll
    for (int i = 0; i < 4; i++) { cp0[i] = 0.f; cp1[i] = 0.f; }

    int grq = rowbase + warpM*64 + (l >> 2);
    #pragma unroll
    for (int mt = 0; mt < 4; ++mt) {
        int gr0 = grq + mt*16;
        int gr1 = gr0 + 8;
        #pragma unroll
        for (int nt = 0; nt < 4; ++nt) {
            const float* cc = &acc[(mt*4+nt)*4];
            int gc0 = colbase + warpN*32 + nt*8 + (l & 3)*2;
            int gc1 = gc0 + 1;
            float e0 = exp20(cc[0]);
            float e1 = exp20(cc[1]);
            float e2 = exp20(cc[2]);
            float e3 = exp20(cc[3]);
            if (isdiag) {
                e0 = (gc0 == gr0) ? 0.f : e0;
                e1 = (gc1 == gr0) ? 0.f : e1;
                e2 = (gc0 == gr1) ? 0.f : e2;
                e3 = (gc1 == gr1) ? 0.f : e3;
            }
            rs[mt*2+0] += e0 + e1;
            rs[mt*2+1] += e2 + e3;
            cp0[nt] += e0 + e2;
            cp1[nt] += e1 + e3;
            // rare path: cosine > 0.7, same label, not self
            if (cc[0] > 0.7f && gc0 != gr0 && g_lab[gc0] == g_lab[gr0]) {
                int idx = atomicAdd(&g_hn, 1);
                if (idx < HCAP) { g_hrow[idx] = gr0; g_hval[idx] = cc[0]*20.f; }
                if (!isdiag) {
                    int idx2 = atomicAdd(&g_hn, 1);
                    if (idx2 < HCAP) { g_hrow[idx2] = gc0; g_hval[idx2] = cc[0]*20.f; }
                }
            }
            if (cc[1] > 0.7f && gc1 != gr0 && g_lab[gc1] == g_lab[gr0]) {
                int idx = atomicAdd(&g_hn, 1);
                if (idx < HCAP) { g_hrow[idx] = gr0; g_hval[idx] = cc[1]*20.f; }
                if (!isdiag) {
                    int idx2 = atomicAdd(&g_hn, 1);
                    if (idx2 < HCAP) { g_hrow[idx2] = gc1; g_hval[idx2] = cc[1]*20.f; }
                }
            }
            if (cc[2] > 0.7f && gc0 != gr1 && g_lab[gc0] == g_lab[gr1]) {
                int idx = atomicAdd(&g_hn, 1);
                if (idx < HCAP) { g_hrow[idx] = gr1; g_hval[idx] = cc[2]*20.f; }
                if (!isdiag) {
                    int idx2 = atomicAdd(&g_hn, 1);
                    if (idx2 < HCAP) { g_hrow[idx2] = gc0; g_hval[idx2] = cc[2]*20.f; }
                }
            }
            if (cc[3] > 0.7f && gc1 != gr1 && g_lab[gc1] == g_lab[gr1]) {
                int idx = atomicAdd(&g_hn, 1);
                if (idx < HCAP) { g_hrow[idx] = gr1; g_hval[idx] = cc[3]*20.f; }
                if (!isdiag) {
                    int idx2 = atomicAdd(&g_hn, 1);
                    if (idx2 < HCAP) { g_hrow[idx2] = gc1; g_hval[idx2] = cc[3]*20.f; }
                }
            }
        }
    }

    // row sums: reduce over the 4 lanes in a quad (same rows), then atomic
    #pragma unroll
    for (int i = 0; i < 8; i++) {
        rs[i] += __shfl_xor_sync(0xffffffffu, rs[i], 1);
        rs[i] += __shfl_xor_sync(0xffffffffu, rs[i], 2);
    }
    if ((l & 3) == 0) {
        #pragma unroll
        for (int i = 0; i < 8; i++) {
            int row = rowbase + warpM*64 + (i >> 1)*16 + (i & 1)*8 + (l >> 2);
            atomicAdd(&g_rowsum[row], rs[i]);
        }
    }
    // column sums (symmetric contribution): reduce over the 8 lanes sharing columns
    if (!isdiag) {
        #pragma unroll
        for (int nt = 0; nt < 4; ++nt) {
            cp0[nt] += __shfl_xor_sync(0xffffffffu, cp0[nt], 4);
            cp0[nt] += __shfl_xor_sync(0xffffffffu, cp0[nt], 8);
            cp0[nt] += __shfl_xor_sync(0xffffffffu, cp0[nt], 16);
            cp1[nt] += __shfl_xor_sync(0xffffffffu, cp1[nt], 4);
            cp1[nt] += __shfl_xor_sync(0xffffffffu, cp1[nt], 8);
            cp1[nt] += __shfl_xor_sync(0xffffffffu, cp1[nt], 16);
        }
        if (l < 4) {
            #pragma unroll
            for (int nt = 0; nt < 4; ++nt) {
                int gc0 = colbase + warpN*32 + nt*8 + l*2;
                atomicAdd(&g_rowsum[gc0], cp0[nt]);
                atomicAdd(&g_rowsum[gc0 + 1], cp1[nt]);
            }
        }
    }
}

// ---------------- finalize ----------------
__global__ void finalize_kernel(float* __restrict__ out) {
    int tid = threadIdx.x;
    double accscl = 0.0, accrel = 0.0;
    for (int i = tid; i < BB; i += 1024) {
        float logd = logf(g_rowsum[i] + 1e-30f);
        int c = g_lab[i];
        float np = (float)(g_cnt[c] - 1);
        float pos = (g_possum[i] - g_selfdot[i]) * 20.f;
        accscl += (double)np*(double)logd - (double)pos;
    }
    __syncthreads();
    int hn = g_hn; if (hn > HCAP) hn = HCAP;
    if (hn > 0) {
        for (int e = tid; e < hn; e += 1024) {
            int r = g_hrow[e];
            atomicAdd(&g_hsum[r], __expf(g_hval[e] - 20.f));
            atomicAdd(&g_hcnt[r], 1);
        }
        __syncthreads();
        for (int i = tid; i < BB; i += 1024) {
            if (g_hcnt[i] > 0)
                accrel += (double)log1pf(g_hsum[i]);
        }
    }
    __shared__ double s1[1024], s2[1024];
    s1[tid] = accscl; s2[tid] = accrel;
    __syncthreads();
    for (int st = 512; st > 0; st >>= 1) {
        if (tid < st) { s1[tid] += s1[tid+st]; s2[tid] += s2[tid+st]; }
        __syncthreads();
    }
    if (tid == 0) {
        double npos = 0.0;
        for (int c = 0; c < NCLS; c++) {
            double cc = (double)g_cnt[c];
            npos += cc*(cc - 1.0);
        }
        double scl = (npos > 0.0) ? s1[0] / fmax(npos, 1.0) : 0.0;
        int hn2 = g_hn; if (hn2 > HCAP) hn2 = HCAP;
        double rel = (hn2 > 0) ? s2[0] / (double)(hn2 > 1 ? hn2 : 1) : 0.0;
        double tot = scl + rel;
        tot = fmin(fmax(tot, 0.0), 10.0);
        out[0] = (float)tot;
    }
}

extern "C" void kernel_launch(void* const* d_in, const int* in_sizes, int n_in,
                              void* d_out, int out_size) {
    const float* feat = (const float*)d_in[0];
    const int* labraw = (const int*)d_in[1];
    float* out = (float*)d_out;

    static bool attr_set = false;
    if (!attr_set) {
        cudaFuncSetAttribute(main_tc, cudaFuncAttributeMaxDynamicSharedMemorySize, SM_TOTAL);
        attr_set = true;
    }

    prep_kernel<<<64, 256>>>(labraw);
    norm_kernel<<<BB/8, 256>>>(feat);
    possum_kernel<<<BB/8, 256>>>();
    main_tc<<<2080, 256, SM_TOTAL>>>();
    finalize_kernel<<<1, 1024>>>(out);
}

// round 12
// speedup vs baseline: 8.8190x; 1.9635x over previous
#include <cuda_runtime.h>
#include <cuda_fp16.h>
#include <math.h>
#include <cstdint>

#define BB 8192
#define DD 256
#define NCLS 128
#define HCAP (1<<20)

// ---------------- scratch ----------------
__device__ int   g_lab[BB];
__device__ float g_fn[BB*DD];
__device__ __half g_h[BB*DD];
__device__ float g_S[NCLS*DD];
__device__ int   g_cnt[NCLS];
__device__ float g_rowsum[BB];
__device__ float g_possum[BB];
__device__ float g_selfdot[BB];
__device__ float g_hsum[BB];
__device__ int   g_hcnt[BB];
__device__ int   g_hn;
__device__ int   g_hrow[HCAP];
__device__ float g_hval[HCAP];

__device__ __forceinline__ uint32_t smem_u32(const void* p) {
    uint32_t a;
    asm("{ .reg .u64 t; cvta.to.shared.u64 t, %1; cvt.u32.u64 %0, t; }" : "=r"(a) : "l"(p));
    return a;
}

#define LDM_X4(r0,r1,r2,r3,addr) \
    asm volatile("ldmatrix.sync.aligned.m8n8.x4.shared.b16 {%0,%1,%2,%3}, [%4];" \
        : "=r"(r0), "=r"(r1), "=r"(r2), "=r"(r3) : "r"(addr))

#define MMA_F16(c, a0,a1,a2,a3, b0,b1) \
    asm volatile("mma.sync.aligned.m16n8k16.row.col.f32.f16.f16.f32 " \
        "{%0,%1,%2,%3}, {%4,%5,%6,%7}, {%8,%9}, {%0,%1,%2,%3};" \
        : "+f"((c)[0]), "+f"((c)[1]), "+f"((c)[2]), "+f"((c)[3]) \
        : "r"(a0), "r"(a1), "r"(a2), "r"(a3), "r"(b0), "r"(b1))

__device__ __forceinline__ void cp16(uint32_t dst, const void* src) {
    asm volatile("cp.async.cg.shared.global [%0], [%1], 16;" :: "r"(dst), "l"(src));
}
#define CP_COMMIT() asm volatile("cp.async.commit_group;" ::: "memory")
#define CP_WAIT(n)  asm volatile("cp.async.wait_group %0;" :: "n"(n) : "memory")

// fast e^{20x}: 2^{x*20*log2e}, degree-6 poly, relerr ~1e-7
__device__ __forceinline__ float exp20(float x) {
    float y = x * 28.853900817779268f;
    float z = y + 12582912.0f;
    int   zi = __float_as_int(z);
    float f = y - (z - 12582912.0f);
    float p = 1.5403530e-4f;
    p = fmaf(p, f, 1.3333558e-3f);
    p = fmaf(p, f, 9.6181291e-3f);
    p = fmaf(p, f, 5.5504109e-2f);
    p = fmaf(p, f, 2.4022651e-1f);
    p = fmaf(p, f, 6.9314718e-1f);
    p = fmaf(p, f, 1.0f);
    return __int_as_float(__float_as_int(p) + (zi << 23));
}

// ---------------- prep ----------------
__global__ void prep_kernel(const int* __restrict__ labraw) {
    __shared__ int is64_s;
    if (threadIdx.x == 0) {
        int all0 = 1;
        #pragma unroll
        for (int i = 0; i < 64; i++) all0 &= (labraw[2*i + 1] == 0);
        is64_s = all0;
    }
    __syncthreads();
    int is64 = is64_s;
    int tid = blockIdx.x*blockDim.x + threadIdx.x;
    int nt = gridDim.x*blockDim.x;
    for (int i = tid; i < BB; i += nt) g_lab[i] = is64 ? labraw[2*i] : labraw[i];
    for (int i = tid; i < NCLS*DD; i += nt) g_S[i] = 0.f;
    for (int i = tid; i < NCLS; i += nt) g_cnt[i] = 0;
    for (int i = tid; i < BB; i += nt) { g_hsum[i] = 0.f; g_hcnt[i] = 0; g_rowsum[i] = 0.f; }
    if (tid == 0) g_hn = 0;
}

// ---------------- normalize + fp16 cast ----------------
__global__ void norm_kernel(const float* __restrict__ feat) {
    int warp = threadIdx.x >> 5, lane = threadIdx.x & 31;
    int row = blockIdx.x*8 + warp;
    const float* fr = feat + (size_t)row*DD;
    float v[8]; float ss = 0.f;
    #pragma unroll
    for (int j = 0; j < 8; j++) { v[j] = fr[lane + j*32]; ss += v[j]*v[j]; }
    #pragma unroll
    for (int off = 16; off > 0; off >>= 1) ss += __shfl_xor_sync(0xffffffffu, ss, off);
    float inv = 1.f / fmaxf(sqrtf(ss), 1e-12f);
    int c = g_lab[row];
    float* fo = g_fn + (size_t)row*DD;
    #pragma unroll
    for (int j = 0; j < 8; j++) {
        float fnv = v[j]*inv;
        fo[lane + j*32] = fnv;
        g_h[(size_t)row*DD + lane + j*32] = __float2half(fnv);
        atomicAdd(&g_S[c*DD + lane + j*32], fnv);
    }
    if (lane == 0) atomicAdd(&g_cnt[c], 1);
}

__global__ void possum_kernel() {
    int warp = threadIdx.x >> 5, lane = threadIdx.x & 31;
    int row = blockIdx.x*8 + warp;
    int c = g_lab[row];
    const float* fr = g_fn + (size_t)row*DD;
    const float* sc = g_S + c*DD;
    float dp = 0.f, sd = 0.f;
    #pragma unroll
    for (int j = 0; j < 8; j++) {
        float a = fr[lane + j*32];
        dp += a*sc[lane + j*32];
        sd += a*a;
    }
    #pragma unroll
    for (int off = 16; off > 0; off >>= 1) {
        dp += __shfl_xor_sync(0xffffffffu, dp, off);
        sd += __shfl_xor_sync(0xffffffffu, sd, off);
    }
    if (lane == 0) { g_possum[row] = dp; g_selfdot[row] = sd; }
}

// ---------------- triangular fp16 mma.sync main kernel ----------------
// One 128x128 tile per CTA, rb <= cb. K chunked by 64, cp.async double-buffered.
#define KC 64
#define STR 72                       // 64 k elems + 8 pad (halves)
#define MAT (128*STR*2)              // 18432 B per matrix per stage
#define STAGE (2*MAT)                // A, B
#define SM_TOTAL (2*STAGE)           // 73728 B -> 2 CTAs/SM

__device__ __forceinline__ void load_chunk(uint32_t sb, int stage,
                                           int rowbase, int colbase, int kc) {
    int tid = threadIdx.x;
    uint32_t sbase = sb + stage*STAGE;
    #pragma unroll
    for (int m = 0; m < 2; m++) {
        int base = (m == 0) ? rowbase : colbase;
        #pragma unroll
        for (int i = 0; i < 4; i++) {
            int idx = tid + i*256;
            int row = idx >> 3;
            int kq = (idx & 7) * 8;
            uint32_t dst = sbase + m*MAT + (uint32_t)(row*STR + kq)*2;
            cp16(dst, &g_h[(size_t)(base+row)*DD + kc*KC + kq]);
        }
    }
}

__global__ void __launch_bounds__(256, 2)
main_tc() {
    extern __shared__ char smem[];
    uint32_t sb = smem_u32(smem);
    int tid = threadIdx.x;
    int wid = tid >> 5, l = tid & 31;
    int warpM = wid >> 2;
    int warpN = wid & 3;

    // decode triangular tile index -> (rb, cb), rb <= cb
    int rb = 0, rem = blockIdx.x;
    while (rem >= 64 - rb) { rem -= 64 - rb; rb++; }
    int cb = rb + rem;
    int rowbase = rb * 128;
    int colbase = cb * 128;
    bool isdiag = (rb == cb);

    uint32_t aOff = (uint32_t)((warpM*64 + (l & 15))*STR*2 + (l >> 4)*16);
    int bRow = (l & 7) + ((l >> 4) << 3);
    uint32_t bOff = (uint32_t)((warpN*32 + bRow)*STR*2 + ((l >> 3) & 1)*16);

    float acc[64];
    #pragma unroll
    for (int i = 0; i < 64; i++) acc[i] = 0.f;

    load_chunk(sb, 0, rowbase, colbase, 0);
    CP_COMMIT();

    #pragma unroll 1
    for (int c = 0; c < 4; ++c) {
        if (c < 3) { load_chunk(sb, (c + 1) & 1, rowbase, colbase, c + 1); CP_COMMIT(); }
        if (c < 3) CP_WAIT(1); else CP_WAIT(0);
        __syncthreads();

        uint32_t st = sb + (c & 1)*STAGE;
        uint32_t sA = st, sB = st + MAT;

        #pragma unroll
        for (int ks = 0; ks < 4; ++ks) {
            uint32_t ka = (uint32_t)(ks*32);
            uint32_t a0[16], b0[8];
            #pragma unroll
            for (int mt = 0; mt < 4; ++mt) {
                uint32_t aa = sA + aOff + (uint32_t)(mt*16*STR*2) + ka;
                LDM_X4(a0[mt*4+0], a0[mt*4+1], a0[mt*4+2], a0[mt*4+3], aa);
            }
            {
                uint32_t bb0 = sB + bOff + ka;
                uint32_t bb1 = bb0 + (uint32_t)(16*STR*2);
                LDM_X4(b0[0], b0[1], b0[2], b0[3], bb0);
                LDM_X4(b0[4], b0[5], b0[6], b0[7], bb1);
            }
            #pragma unroll
            for (int mt = 0; mt < 4; ++mt)
                #pragma unroll
                for (int nt = 0; nt < 4; ++nt)
                    MMA_F16(&acc[(mt*4+nt)*4], a0[mt*4+0], a0[mt*4+1], a0[mt*4+2], a0[mt*4+3],
                            b0[nt*2+0], b0[nt*2+1]);
        }
        __syncthreads();
    }

    // ---- epilogue: scatter exp into row sums and (off-diag) column sums ----
    float rs[8];
    float cp0[4], cp1[4];
    #pragma unroll
    for (int i = 0; i < 8; i++) rs[i] = 0.f;
    #pragma unroll
    for (int i = 0; i < 4; i++) { cp0[i] = 0.f; cp1[i] = 0.f; }

    int grq = rowbase + warpM*64 + (l >> 2);
    #pragma unroll
    for (int mt = 0; mt < 4; ++mt) {
        int gr0 = grq + mt*16;
        int gr1 = gr0 + 8;
        #pragma unroll
        for (int nt = 0; nt < 4; ++nt) {
            const float* cc = &acc[(mt*4+nt)*4];
            int gc0 = colbase + warpN*32 + nt*8 + (l & 3)*2;
            int gc1 = gc0 + 1;
            float e0 = exp20(cc[0]);
            float e1 = exp20(cc[1]);
            float e2 = exp20(cc[2]);
            float e3 = exp20(cc[3]);
            if (isdiag) {
                e0 = (gc0 == gr0) ? 0.f : e0;
                e1 = (gc1 == gr0) ? 0.f : e1;
                e2 = (gc0 == gr1) ? 0.f : e2;
                e3 = (gc1 == gr1) ? 0.f : e3;
            }
            rs[mt*2+0] += e0 + e1;
            rs[mt*2+1] += e2 + e3;
            cp0[nt] += e0 + e2;
            cp1[nt] += e1 + e3;
            // rare path: cosine > 0.7, same label, not self
            if (cc[0] > 0.7f && gc0 != gr0 && g_lab[gc0] == g_lab[gr0]) {
                int idx = atomicAdd(&g_hn, 1);
                if (idx < HCAP) { g_hrow[idx] = gr0; g_hval[idx] = cc[0]*20.f; }
                if (!isdiag) {
                    int idx2 = atomicAdd(&g_hn, 1);
                    if (idx2 < HCAP) { g_hrow[idx2] = gc0; g_hval[idx2] = cc[0]*20.f; }
                }
            }
            if (cc[1] > 0.7f && gc1 != gr0 && g_lab[gc1] == g_lab[gr0]) {
                int idx = atomicAdd(&g_hn, 1);
                if (idx < HCAP) { g_hrow[idx] = gr0; g_hval[idx] = cc[1]*20.f; }
                if (!isdiag) {
                    int idx2 = atomicAdd(&g_hn, 1);
                    if (idx2 < HCAP) { g_hrow[idx2] = gc1; g_hval[idx2] = cc[1]*20.f; }
                }
            }
            if (cc[2] > 0.7f && gc0 != gr1 && g_lab[gc0] == g_lab[gr1]) {
                int idx = atomicAdd(&g_hn, 1);
                if (idx < HCAP) { g_hrow[idx] = gr1; g_hval[idx] = cc[2]*20.f; }
                if (!isdiag) {
                    int idx2 = atomicAdd(&g_hn, 1);
                    if (idx2 < HCAP) { g_hrow[idx2] = gc0; g_hval[idx2] = cc[2]*20.f; }
                }
            }
            if (cc[3] > 0.7f && gc1 != gr1 && g_lab[gc1] == g_lab[gr1]) {
                int idx = atomicAdd(&g_hn, 1);
                if (idx < HCAP) { g_hrow[idx] = gr1; g_hval[idx] = cc[3]*20.f; }
                if (!isdiag) {
                    int idx2 = atomicAdd(&g_hn, 1);
                    if (idx2 < HCAP) { g_hrow[idx2] = gc1; g_hval[idx2] = cc[3]*20.f; }
                }
            }
        }
    }

    // row sums: reduce over the 4 lanes in a quad (same rows), then atomic
    #pragma unroll
    for (int i = 0; i < 8; i++) {
        rs[i] += __shfl_xor_sync(0xffffffffu, rs[i], 1);
        rs[i] += __shfl_xor_sync(0xffffffffu, rs[i], 2);
    }
    if ((l & 3) == 0) {
        #pragma unroll
        for (int i = 0; i < 8; i++) {
            int row = rowbase + warpM*64 + (i >> 1)*16 + (i & 1)*8 + (l >> 2);
            atomicAdd(&g_rowsum[row], rs[i]);
        }
    }
    // column sums (symmetric contribution): reduce over the 8 lanes sharing columns
    if (!isdiag) {
        #pragma unroll
        for (int nt = 0; nt < 4; ++nt) {
            cp0[nt] += __shfl_xor_sync(0xffffffffu, cp0[nt], 4);
            cp0[nt] += __shfl_xor_sync(0xffffffffu, cp0[nt], 8);
            cp0[nt] += __shfl_xor_sync(0xffffffffu, cp0[nt], 16);
            cp1[nt] += __shfl_xor_sync(0xffffffffu, cp1[nt], 4);
            cp1[nt] += __shfl_xor_sync(0xffffffffu, cp1[nt], 8);
            cp1[nt] += __shfl_xor_sync(0xffffffffu, cp1[nt], 16);
        }
        if (l < 4) {
            #pragma unroll
            for (int nt = 0; nt < 4; ++nt) {
                int gc0 = colbase + warpN*32 + nt*8 + l*2;
                atomicAdd(&g_rowsum[gc0], cp0[nt]);
                atomicAdd(&g_rowsum[gc0 + 1], cp1[nt]);
            }
        }
    }
}

// ---------------- finalize ----------------
__global__ void finalize_kernel(float* __restrict__ out) {
    int tid = threadIdx.x;
    double accscl = 0.0, accrel = 0.0;
    for (int i = tid; i < BB; i += 1024) {
        float logd = logf(g_rowsum[i] + 1e-30f);
        int c = g_lab[i];
        float np = (float)(g_cnt[c] - 1);
        float pos = (g_possum[i] - g_selfdot[i]) * 20.f;
        accscl += (double)np*(double)logd - (double)pos;
    }
    __syncthreads();
    int hn = g_hn; if (hn > HCAP) hn = HCAP;
    if (hn > 0) {
        for (int e = tid; e < hn; e += 1024) {
            int r = g_hrow[e];
            atomicAdd(&g_hsum[r], __expf(g_hval[e] - 20.f));
            atomicAdd(&g_hcnt[r], 1);
        }
        __syncthreads();
        for (int i = tid; i < BB; i += 1024) {
            if (g_hcnt[i] > 0)
                accrel += (double)log1pf(g_hsum[i]);
        }
    }
    __shared__ double s1[1024], s2[1024];
    s1[tid] = accscl; s2[tid] = accrel;
    __syncthreads();
    for (int st = 512; st > 0; st >>= 1) {
        if (tid < st) { s1[tid] += s1[tid+st]; s2[tid] += s2[tid+st]; }
        __syncthreads();
    }
    if (tid == 0) {
        double npos = 0.0;
        for (int c = 0; c < NCLS; c++) {
            double cc = (double)g_cnt[c];
            npos += cc*(cc - 1.0);
        }
        double scl = (npos > 0.0) ? s1[0] / fmax(npos, 1.0) : 0.0;
        int hn2 = g_hn; if (hn2 > HCAP) hn2 = HCAP;
        double rel = (hn2 > 0) ? s2[0] / (double)(hn2 > 1 ? hn2 : 1) : 0.0;
        double tot = scl + rel;
        tot = fmin(fmax(tot, 0.0), 10.0);
        out[0] = (float)tot;
    }
}

extern "C" void kernel_launch(void* const* d_in, const int* in_sizes, int n_in,
                              void* d_out, int out_size) {
    const float* feat = (const float*)d_in[0];
    const int* labraw = (const int*)d_in[1];
    float* out = (float*)d_out;

    static bool attr_set = false;
    if (!attr_set) {
        cudaFuncSetAttribute(main_tc, cudaFuncAttributeMaxDynamicSharedMemorySize, SM_TOTAL);
        attr_set = true;
    }

    prep_kernel<<<64, 256>>>(labraw);
    norm_kernel<<<BB/8, 256>>>(feat);
    possum_kernel<<<BB/8, 256>>>();
    main_tc<<<2080, 256, SM_TOTAL>>>();
    finalize_kernel<<<1, 1024>>>(out);
}